// round 11
// baseline (speedup 1.0000x reference)
#include <cuda_runtime.h>
#include <cuda_fp16.h>
#include <mma.h>
#include <math.h>

using namespace nvcuda;

// ----- problem constants -----
#define BB    2
#define AA    900
#define EDD   256
#define NGRP  8
#define NCAM  6
#define NLVL  4
#define NPT   7
#define NW    1344            // NGRP*NCAM*NLVL*NPT
#define NBA   (BB*AA)         // 1800
#define MPAD  1920
#define NDESC (NCAM*NPT*NLVL) // 168
#define NBC   (BB*NCAM)       // 12

// level geometry
#define HW0 11264
#define HW1 2816
#define HW2 704
#define HW3 176
#define PB0 0
#define PB1 (NBC*HW0)
#define PB2 (PB1 + NBC*HW1)
#define PB3 (PB2 + NBC*HW2)
#define NPIX (PB3 + NBC*HW3)           // 179520

// conversion blocks
#define CT0 176
#define CT1 44
#define CT2 11
#define CT3 3
#define CV0 (NBC*CT0*4)
#define CV1 (NBC*CT1*4)
#define CV2 (NBC*CT2*4)
#define CV3 (NBC*CT3*4)
#define CVTOT (CV0+CV1+CV2+CV3)        // 11232

#define GEMM_BLKS ((NW/32) * (MPAD/128))   // 42*15 = 630
#define WOUT_BLKS 64

// ----- scratch (allocation-free: device globals; zero-initialized) -----
__device__ __align__(16) __half g_woutH[EDD * EDD];
__device__ __align__(16) float  g_w[MPAD * NW];
__device__ __align__(16) __half g_fusedH[MPAD * EDD];
__device__ __align__(16) __half g_nhwc[(size_t)NPIX * EDD];

// =====================================================================
// Fused kernel (256 threads, reg-capped for conversion occupancy):
//   [0, GEMM_BLKS): wmma FC GEMM, 128m x 32n tile (low reg)
//   [GEMM_BLKS, +CVTOT): NCHW fp32 -> NHWC fp16 conversion
//   [+CVTOT, +WOUT_BLKS): w_out fp32 -> fp16
// GEMM blocks first: they soak into wave 1 and hide under the
// conversion's DRAM-bound tail.
// =====================================================================
__global__ void __launch_bounds__(256, 6) fused_kernel(
    const float* __restrict__ inst, const float* __restrict__ emb,
    const float* __restrict__ w_fc, const float* __restrict__ w_out,
    const float* __restrict__ f0, const float* __restrict__ f1,
    const float* __restrict__ f2, const float* __restrict__ f3)
{
    __shared__ __align__(16) unsigned char smraw[16896];
    const int tid = threadIdx.x;

    if (blockIdx.x < GEMM_BLKS) {
        // ---- FC GEMM: g_w[MPAD][NW] = (inst+emb) @ w_fc^T -------------
        __half* sA = (__half*)smraw;            // [128][32]  8KB
        __half* sB = (__half*)(smraw + 8192);   // [32][32]   2KB
        const int gx = blockIdx.x % (NW / 32);
        const int gy = blockIdx.x / (NW / 32);
        const int bm0 = gy * 128;
        const int bn0 = gx * 32;
        const int wid = tid >> 5;
        const int wm  = wid & 3;                // 4 warps in m
        const int wn  = wid >> 2;               // 2 warps in n
        const int m0 = wm * 32;
        const int n0 = wn * 16;

        wmma::fragment<wmma::accumulator, 16, 16, 16, float> cf[2];
#pragma unroll
        for (int i = 0; i < 2; i++) wmma::fill_fragment(cf[i], 0.f);

        for (int kt = 0; kt < 256; kt += 32) {
            // stage A: 128 rows x 32 k (fp32 -> fp16)
#pragma unroll
            for (int s = 0; s < 4; s++) {
                int id = tid + s * 256;
                int row = id >> 3, q = id & 7;
                int m = bm0 + row;
                float4 v = make_float4(0.f, 0.f, 0.f, 0.f);
                if (m < NBA) {
                    v = *(const float4*)(inst + (size_t)m * 256 + kt + q * 4);
                    float4 w = *(const float4*)(emb + (size_t)m * 256 + kt + q * 4);
                    v.x += w.x; v.y += w.y; v.z += w.z; v.w += w.w;
                }
                __half2* d = (__half2*)&sA[row * 32 + q * 4];
                d[0] = __floats2half2_rn(v.x, v.y);
                d[1] = __floats2half2_rn(v.z, v.w);
            }
            // stage B: 32 rows (n) x 32 k — exactly 256 lanes
            {
                int row = tid >> 3, q = tid & 7;
                int n = bn0 + row;
                float4 v = *(const float4*)(w_fc + (size_t)n * 256 + kt + q * 4);
                __half2* d = (__half2*)&sB[row * 32 + q * 4];
                d[0] = __floats2half2_rn(v.x, v.y);
                d[1] = __floats2half2_rn(v.z, v.w);
            }
            __syncthreads();

#pragma unroll
            for (int kk = 0; kk < 2; kk++) {
                wmma::fragment<wmma::matrix_a, 16, 16, 16, __half, wmma::row_major> af;
                wmma::fragment<wmma::matrix_b, 16, 16, 16, __half, wmma::col_major> bf;
                wmma::load_matrix_sync(bf, sB + n0 * 32 + kk * 16, 32);
#pragma unroll
                for (int i = 0; i < 2; i++) {
                    wmma::load_matrix_sync(af, sA + (m0 + i * 16) * 32 + kk * 16, 32);
                    wmma::mma_sync(cf[i], af, bf, cf[i]);
                }
            }
            __syncthreads();
        }
#pragma unroll
        for (int i = 0; i < 2; i++)
            wmma::store_matrix_sync(g_w + (size_t)(bm0 + m0 + i * 16) * NW + bn0 + n0,
                                    cf[i], NW, wmma::mem_row_major);
    } else if (blockIdx.x < GEMM_BLKS + CVTOT) {
        // ------- NCHW fp32 -> NHWC fp16, 64ch x 64px tile ---------------
        int cb = blockIdx.x - GEMM_BLKS;
        const float* fin; int HWl, tilesHW, pbase;
        if (cb < CV0)               { fin = f0; HWl = HW0; tilesHW = CT0; pbase = PB0; }
        else if ((cb -= CV0) < CV1) { fin = f1; HWl = HW1; tilesHW = CT1; pbase = PB1; }
        else if ((cb -= CV1) < CV2) { fin = f2; HWl = HW2; tilesHW = CT2; pbase = PB2; }
        else       { cb -= CV2;       fin = f3; HWl = HW3; tilesHW = CT3; pbase = PB3; }
        const int nt  = tilesHW * 4;
        const int bc  = cb / nt;
        const int r   = cb % nt;
        const int hw0 = (r >> 2) * 64;
        const int c0  = (r & 3) * 64;
        float (*t)[65] = (float(*)[65])smraw;

        const float* ip = fin + (size_t)bc * 256 * HWl;
#pragma unroll
        for (int s = 0; s < 4; s++) {
            int id = tid + s * 256;
            int row = id >> 4, q = id & 15;
            int hw = hw0 + q * 4;
            if (hw < HWl) {
                float4 v = __ldcs((const float4*)(ip + (size_t)(c0 + row) * HWl + hw));
                t[row][q * 4 + 0] = v.x;
                t[row][q * 4 + 1] = v.y;
                t[row][q * 4 + 2] = v.z;
                t[row][q * 4 + 3] = v.w;
            }
        }
        __syncthreads();
        __half* op = g_nhwc + ((size_t)(pbase + bc * HWl)) * 256;
#pragma unroll
        for (int s = 0; s < 4; s++) {
            int id = tid + s * 256;
            int px = id >> 4, qc = id & 15;
            int hw = hw0 + px;
            if (hw < HWl) {
                __half2 h0 = __floats2half2_rn(t[qc * 4 + 0][px], t[qc * 4 + 1][px]);
                __half2 h1 = __floats2half2_rn(t[qc * 4 + 2][px], t[qc * 4 + 3][px]);
                uint2 o;
                o.x = *(unsigned*)&h0;
                o.y = *(unsigned*)&h1;
                *(uint2*)(op + (size_t)hw * 256 + c0 + qc * 4) = o;
            }
        }
    } else {
        // ------- w_out fp32 -> fp16 -------------------------------------
        int j = (blockIdx.x - GEMM_BLKS - CVTOT) * 256 + tid;   // float4 idx
        float4 v = *(const float4*)(w_out + (size_t)j * 4);
        __half2 h0 = __floats2half2_rn(v.x, v.y);
        __half2 h1 = __floats2half2_rn(v.z, v.w);
        uint2 o;
        o.x = *(unsigned*)&h0;
        o.y = *(unsigned*)&h1;
        *(uint2*)(g_woutH + (size_t)j * 4) = o;
    }
}

// =====================================================================
// Fused aggregation: 128 threads / 4 warps; lane covers 8 channels
// (uint4 gathers); warps split the descriptor list 4 ways.
// =====================================================================
__global__ void __launch_bounds__(128) agg_kernel(
    const float* __restrict__ anchor, const float* __restrict__ proj,
    const float* __restrict__ wh, const float* __restrict__ b_fc)
{
    __shared__ float  s_w[NW];
    __shared__ float  s_uv[NCAM * NPT][2];
    __shared__ int4   s_dA[NDESC];
    __shared__ float4 s_dW[NDESC];
    __shared__ int    s_cnt[8];
    __shared__ float  s_acc[4][EDD];

    const int ba   = blockIdx.x;
    const int b    = ba / AA;
    const int tid  = threadIdx.x;    // 0..127
    const int wrp  = tid >> 5;       // 0..3
    const int lane = tid & 31;

    for (int i = tid; i < NW; i += 128) s_w[i] = g_w[(size_t)ba * NW + i] + b_fc[i];

    if (tid < NCAM * NPT) {
        const float fsx[7] = {0.f, 0.45f, -0.45f, 0.f, 0.f, 0.f, 0.f};
        const float fsy[7] = {0.f, 0.f, 0.f, 0.45f, -0.45f, 0.f, 0.f};
        const float fsz[7] = {0.f, 0.f, 0.f, 0.f, 0.f, 0.45f, -0.45f};
        int cam = tid / NPT, p = tid % NPT;
        const float* an = anchor + (size_t)ba * 8;
        float e0 = expf(an[3]), e1 = expf(an[4]), e2 = expf(an[5]);
        float k0 = fsx[p] * e0, k1 = fsy[p] * e1, k2 = fsz[p] * e2;
        float sn = an[6], cs = an[7];
        float X = cs * k0 - sn * k1 + an[0];
        float Y = sn * k0 + cs * k1 + an[1];
        float Z = k2 + an[2];
        const float* M = proj + (size_t)(b * NCAM + cam) * 16;
        float d0 = M[0] * X + M[1] * Y + M[2]  * Z + M[3];
        float d1 = M[4] * X + M[5] * Y + M[6]  * Z + M[7];
        float d2 = M[8] * X + M[9] * Y + M[10] * Z + M[11];
        float iz = 1.f / fmaxf(d2, 1e-5f);
        float x = d0 * iz / fmaxf(wh[(size_t)(b * NCAM + cam) * 2 + 0], 1e-5f);
        float y = d1 * iz / fmaxf(wh[(size_t)(b * NCAM + cam) * 2 + 1], 1e-5f);
        s_uv[tid][0] = x * 2.f - 1.f;
        s_uv[tid][1] = y * 2.f - 1.f;
    }
    __syncthreads();

    // softmax: warp wrp -> groups wrp*2, wrp*2+1
#pragma unroll
    for (int q = 0; q < 2; q++) {
        int gg = wrp * 2 + q;
        float mx = -INFINITY;
        for (int cc = lane; cc < 168; cc += 32) mx = fmaxf(mx, s_w[cc * 8 + gg]);
#pragma unroll
        for (int o = 16; o; o >>= 1) mx = fmaxf(mx, __shfl_xor_sync(0xffffffffu, mx, o));
        float sum = 0.f;
        for (int cc = lane; cc < 168; cc += 32) {
            float e = expf(s_w[cc * 8 + gg] - mx);
            s_w[cc * 8 + gg] = e;
            sum += e;
        }
#pragma unroll
        for (int o = 16; o; o >>= 1) sum += __shfl_xor_sync(0xffffffffu, sum, o);
        float inv = 1.f / sum;
        for (int cc = lane; cc < 168; cc += 32) s_w[cc * 8 + gg] *= inv;
    }

    // descriptors: 168 over 128 threads, 2 iterations + compaction
    const int Hl[4]  = {64, 32, 16, 8};
    const int Wl[4]  = {176, 88, 44, 22};
    const int HWl[4] = {HW0, HW1, HW2, HW3};
    const int PBl[4] = {PB0, PB1, PB2, PB3};
    int4   dA2[2];
    float4 dW2[2];
    unsigned bal2[2];
    int flags = 0;
#pragma unroll
    for (int it = 0; it < 2; it++) {
        int d = it * 128 + tid;
        int flag = 0;
        if (d < NDESC) {
            int cam = d / (NPT * NLVL);
            int r   = d - cam * (NPT * NLVL);
            int p   = r >> 2;
            int lvl = r & 3;
            float u = s_uv[cam * NPT + p][0];
            float v = s_uv[cam * NPT + p][1];
            const int H = Hl[lvl], W = Wl[lvl];
            float gx = (u + 1.f) * (W * 0.5f) - 0.5f;
            float gy = (v + 1.f) * (H * 0.5f) - 0.5f;
            float x0f = floorf(gx), y0f = floorf(gy);
            float wx1 = gx - x0f, wy1 = gy - y0f;
            bool vx0 = (x0f >= 0.f)       && (x0f <= (float)(W - 1));
            bool vx1 = (x0f + 1.f >= 0.f) && (x0f + 1.f <= (float)(W - 1));
            bool vy0 = (y0f >= 0.f)       && (y0f <= (float)(H - 1));
            bool vy1 = (y0f + 1.f >= 0.f) && (y0f + 1.f <= (float)(H - 1));
            flag = ((vx0 || vx1) && (vy0 || vy1)) ? 1 : 0;
            int x0 = (int)fminf(fmaxf(x0f, 0.f),       (float)(W - 1));
            int x1 = (int)fminf(fmaxf(x0f + 1.f, 0.f), (float)(W - 1));
            int y0 = (int)fminf(fmaxf(y0f, 0.f),       (float)(H - 1));
            int y1 = (int)fminf(fmaxf(y0f + 1.f, 0.f), (float)(H - 1));
            dA2[it].x = PBl[lvl] + (b * NCAM + cam) * HWl[lvl] + y0 * W + x0;
            dA2[it].y = (x1 - x0) * 256;
            dA2[it].z = (y1 - y0) * W * 256;
            dA2[it].w = ((cam * NLVL + lvl) * NPT + p) * NGRP;
            dW2[it].x = (vx0 && vy0) ? (1.f - wx1) * (1.f - wy1) : 0.f;
            dW2[it].y = (vx1 && vy0) ? wx1 * (1.f - wy1)         : 0.f;
            dW2[it].z = (vx0 && vy1) ? (1.f - wx1) * wy1         : 0.f;
            dW2[it].w = (vx1 && vy1) ? wx1 * wy1                 : 0.f;
        }
        bal2[it] = __ballot_sync(0xffffffffu, flag);
        flags |= flag << it;
        if (lane == 0) s_cnt[it * 4 + wrp] = __popc(bal2[it]);
    }
    __syncthreads();

    int pfx[8];
    {
        int run = 0;
#pragma unroll
        for (int i = 0; i < 8; i++) { pfx[i] = run; run += s_cnt[i]; }
    }
    int cnt = pfx[7] + s_cnt[7];
#pragma unroll
    for (int it = 0; it < 2; it++) {
        if ((flags >> it) & 1) {
            int pos = pfx[it * 4 + wrp] + __popc(bal2[it] & ((1u << lane) - 1u));
            s_dA[pos] = dA2[it];
            s_dW[pos] = dW2[it];
        }
    }
    __syncthreads();

    // gather + fuse: lane -> channels lane*8..+7; warp strides desc by 4
    const int g = lane >> 2;
    const __half* chan = g_nhwc + lane * 8;
    float a[8];
#pragma unroll
    for (int q = 0; q < 8; q++) a[q] = 0.f;

    for (int i = wrp; i < cnt; i += 4) {
        int4 D = s_dA[i];
        float4 wt = s_dW[i];
        const __half* bp = chan + (((size_t)D.x) << 8);
        uint4 r00 = *(const uint4*)(bp);
        uint4 r01 = *(const uint4*)(bp + D.y);
        uint4 r10 = *(const uint4*)(bp + D.z);
        uint4 r11 = *(const uint4*)(bp + D.z + D.y);
        float wf = s_w[D.w + g];
        const unsigned* p00 = &r00.x;
        const unsigned* p01 = &r01.x;
        const unsigned* p10 = &r10.x;
        const unsigned* p11 = &r11.x;
#pragma unroll
        for (int q = 0; q < 4; q++) {
            float2 v00 = __half22float2(*(const __half2*)&p00[q]);
            float2 v01 = __half22float2(*(const __half2*)&p01[q]);
            float2 v10 = __half22float2(*(const __half2*)&p10[q]);
            float2 v11 = __half22float2(*(const __half2*)&p11[q]);
            float sx = fmaf(wt.x, v00.x, fmaf(wt.y, v01.x, fmaf(wt.z, v10.x, wt.w * v11.x)));
            float sy = fmaf(wt.x, v00.y, fmaf(wt.y, v01.y, fmaf(wt.z, v10.y, wt.w * v11.y)));
            a[q * 2 + 0] = fmaf(sx, wf, a[q * 2 + 0]);
            a[q * 2 + 1] = fmaf(sy, wf, a[q * 2 + 1]);
        }
    }
#pragma unroll
    for (int q = 0; q < 8; q++) s_acc[wrp][lane * 8 + q] = a[q];
    __syncthreads();

    // combine 4 warps' partials, store fp16 row-major (2 ch per thread)
    {
        int c = tid * 2;
        float o0 = s_acc[0][c + 0] + s_acc[1][c + 0] + s_acc[2][c + 0] + s_acc[3][c + 0];
        float o1 = s_acc[0][c + 1] + s_acc[1][c + 1] + s_acc[2][c + 1] + s_acc[3][c + 1];
        *(__half2*)(g_fusedH + (size_t)ba * EDD + c) = __floats2half2_rn(o0, o1);
    }
}

// =====================================================================
// Out-projection wmma: 32m x 64n tiles, 8 warps (2n x 4k split-K).
// =====================================================================
__global__ void __launch_bounds__(256) outproj_wmma(
    const float* __restrict__ bias, float* __restrict__ out)
{
    __shared__ __align__(16) float sm[4][32][72];
    const int bx = blockIdx.x;
    const int by = blockIdx.y;
    const int tid = threadIdx.x;
    const int wid = tid >> 5;
    const int wk  = wid >> 1;
    const int wn  = wid & 1;
    const int m0 = by * 32;
    const int n0 = bx * 64 + wn * 32;

    wmma::fragment<wmma::accumulator, 16, 16, 16, float> cf[2][2];
#pragma unroll
    for (int i = 0; i < 2; i++)
#pragma unroll
        for (int j = 0; j < 2; j++) wmma::fill_fragment(cf[i][j], 0.f);

    for (int k0 = wk * 64; k0 < wk * 64 + 64; k0 += 16) {
        wmma::fragment<wmma::matrix_a, 16, 16, 16, __half, wmma::row_major> af[2];
        wmma::fragment<wmma::matrix_b, 16, 16, 16, __half, wmma::col_major> bf[2];
#pragma unroll
        for (int i = 0; i < 2; i++)
            wmma::load_matrix_sync(af[i], g_fusedH + (size_t)(m0 + i * 16) * EDD + k0, EDD);
#pragma unroll
        for (int j = 0; j < 2; j++)
            wmma::load_matrix_sync(bf[j], g_woutH + (size_t)(n0 + j * 16) * EDD + k0, EDD);
#pragma unroll
        for (int i = 0; i < 2; i++)
#pragma unroll
            for (int j = 0; j < 2; j++)
                wmma::mma_sync(cf[i][j], af[i], bf[j], cf[i][j]);
    }
#pragma unroll
    for (int i = 0; i < 2; i++)
#pragma unroll
        for (int j = 0; j < 2; j++)
            wmma::store_matrix_sync(&sm[wk][i * 16][wn * 32 + j * 16],
                                    cf[i][j], 72, wmma::mem_row_major);
    __syncthreads();

    const int c = (tid & 15) * 4;
    float4 bb = *(const float4*)(bias + bx * 64 + c);
    for (int r = (tid >> 4); r < 32; r += 16) {
        int m = by * 32 + r;
        if (m >= NBA) break;
        float4 o;
        o.x = sm[0][r][c + 0] + sm[1][r][c + 0] + sm[2][r][c + 0] + sm[3][r][c + 0] + bb.x;
        o.y = sm[0][r][c + 1] + sm[1][r][c + 1] + sm[2][r][c + 1] + sm[3][r][c + 1] + bb.y;
        o.z = sm[0][r][c + 2] + sm[1][r][c + 2] + sm[2][r][c + 2] + sm[3][r][c + 2] + bb.z;
        o.w = sm[0][r][c + 3] + sm[1][r][c + 3] + sm[2][r][c + 3] + sm[3][r][c + 3] + bb.w;
        *(float4*)(out + (size_t)m * EDD + bx * 64 + c) = o;
    }
}

// =====================================================================
// launch
// =====================================================================
extern "C" void kernel_launch(void* const* d_in, const int* in_sizes, int n_in,
                              void* d_out, int out_size)
{
    const float* inst   = (const float*)d_in[0];
    const float* anchor = (const float*)d_in[1];
    const float* emb    = (const float*)d_in[2];
    const float* f0     = (const float*)d_in[3];
    const float* f1     = (const float*)d_in[4];
    const float* f2     = (const float*)d_in[5];
    const float* f3     = (const float*)d_in[6];
    const float* proj   = (const float*)d_in[7];
    const float* wh     = (const float*)d_in[8];
    const float* w_fc   = (const float*)d_in[9];
    const float* b_fc   = (const float*)d_in[10];
    const float* w_out  = (const float*)d_in[11];
    const float* b_out  = (const float*)d_in[12];
    float* out = (float*)d_out;

    fused_kernel<<<GEMM_BLKS + CVTOT + WOUT_BLKS, 256>>>(
        inst, emb, w_fc, w_out, f0, f1, f2, f3);
    agg_kernel<<<NBA, 128>>>(anchor, proj, wh, b_fc);
    outproj_wmma<<<dim3(EDD / 64, MPAD / 32), 256>>>(b_out, out);
}

// round 12
// speedup vs baseline: 1.0349x; 1.0349x over previous
#include <cuda_runtime.h>
#include <cuda_fp16.h>
#include <mma.h>
#include <math.h>

using namespace nvcuda;

// ----- problem constants -----
#define BB    2
#define AA    900
#define EDD   256
#define NGRP  8
#define NCAM  6
#define NLVL  4
#define NPT   7
#define NW    1344            // NGRP*NCAM*NLVL*NPT
#define NBA   (BB*AA)         // 1800
#define MPAD  1920
#define NDESC (NCAM*NPT*NLVL) // 168
#define NBC   (BB*NCAM)       // 12

// level geometry
#define HW0 11264
#define HW1 2816
#define HW2 704
#define HW3 176
#define PB0 0
#define PB1 (NBC*HW0)
#define PB2 (PB1 + NBC*HW1)
#define PB3 (PB2 + NBC*HW2)
#define NPIX (PB3 + NBC*HW3)           // 179520

// conversion blocks
#define CT0 176
#define CT1 44
#define CT2 11
#define CT3 3
#define CV0 (NBC*CT0*4)
#define CV1 (NBC*CT1*4)
#define CV2 (NBC*CT2*4)
#define CV3 (NBC*CT3*4)
#define CVTOT (CV0+CV1+CV2+CV3)        // 11232

#define GEMM_BLKS ((NW/32) * (MPAD/128))   // 630
#define WOUT_BLKS 64

// ----- scratch (allocation-free: device globals; zero-initialized) -----
__device__ __align__(16) __half g_woutH[EDD * EDD];
__device__ __align__(16) float  g_w[MPAD * NW];
__device__ __align__(16) __half g_fusedH[MPAD * EDD];
__device__ __align__(16) __half g_nhwc[(size_t)NPIX * EDD];

// =====================================================================
// Fused kernel (256 threads, reg-capped):
//   [0, GEMM_BLKS): wmma FC GEMM, 128m x 32n tile
//   [GEMM_BLKS, +CVTOT): NCHW fp32 -> NHWC fp16, half-packed transpose
//   [+CVTOT, +WOUT_BLKS): w_out fp32 -> fp16
// =====================================================================
__global__ void __launch_bounds__(256, 6) fused_kernel(
    const float* __restrict__ inst, const float* __restrict__ emb,
    const float* __restrict__ w_fc, const float* __restrict__ w_out,
    const float* __restrict__ f0, const float* __restrict__ f1,
    const float* __restrict__ f2, const float* __restrict__ f3)
{
    __shared__ __align__(16) unsigned char smraw[10496];
    const int tid = threadIdx.x;

    if (blockIdx.x < GEMM_BLKS) {
        // ---- FC GEMM: g_w[MPAD][NW] = (inst+emb) @ w_fc^T -------------
        __half* sA = (__half*)smraw;            // [128][32]  8KB
        __half* sB = (__half*)(smraw + 8192);   // [32][32]   2KB
        const int gx = blockIdx.x % (NW / 32);
        const int gy = blockIdx.x / (NW / 32);
        const int bm0 = gy * 128;
        const int bn0 = gx * 32;
        const int wid = tid >> 5;
        const int wm  = wid & 3;
        const int wn  = wid >> 2;
        const int m0 = wm * 32;
        const int n0 = wn * 16;

        wmma::fragment<wmma::accumulator, 16, 16, 16, float> cf[2];
#pragma unroll
        for (int i = 0; i < 2; i++) wmma::fill_fragment(cf[i], 0.f);

        for (int kt = 0; kt < 256; kt += 32) {
#pragma unroll
            for (int s = 0; s < 4; s++) {
                int id = tid + s * 256;
                int row = id >> 3, q = id & 7;
                int m = bm0 + row;
                float4 v = make_float4(0.f, 0.f, 0.f, 0.f);
                if (m < NBA) {
                    v = *(const float4*)(inst + (size_t)m * 256 + kt + q * 4);
                    float4 w = *(const float4*)(emb + (size_t)m * 256 + kt + q * 4);
                    v.x += w.x; v.y += w.y; v.z += w.z; v.w += w.w;
                }
                __half2* d = (__half2*)&sA[row * 32 + q * 4];
                d[0] = __floats2half2_rn(v.x, v.y);
                d[1] = __floats2half2_rn(v.z, v.w);
            }
            {
                int row = tid >> 3, q = tid & 7;
                int n = bn0 + row;
                float4 v = *(const float4*)(w_fc + (size_t)n * 256 + kt + q * 4);
                __half2* d = (__half2*)&sB[row * 32 + q * 4];
                d[0] = __floats2half2_rn(v.x, v.y);
                d[1] = __floats2half2_rn(v.z, v.w);
            }
            __syncthreads();

#pragma unroll
            for (int kk = 0; kk < 2; kk++) {
                wmma::fragment<wmma::matrix_a, 16, 16, 16, __half, wmma::row_major> af;
                wmma::fragment<wmma::matrix_b, 16, 16, 16, __half, wmma::col_major> bf;
                wmma::load_matrix_sync(bf, sB + n0 * 32 + kk * 16, 32);
#pragma unroll
                for (int i = 0; i < 2; i++) {
                    wmma::load_matrix_sync(af, sA + (m0 + i * 16) * 32 + kk * 16, 32);
                    wmma::mma_sync(cf[i], af, bf, cf[i]);
                }
            }
            __syncthreads();
        }
#pragma unroll
        for (int i = 0; i < 2; i++)
            wmma::store_matrix_sync(g_w + (size_t)(bm0 + m0 + i * 16) * NW + bn0 + n0,
                                    cf[i], NW, wmma::mem_row_major);
    } else if (blockIdx.x < GEMM_BLKS + CVTOT) {
        // ---- NCHW fp32 -> NHWC fp16, 64ch x 64px, half-packed ---------
        int cb = blockIdx.x - GEMM_BLKS;
        const float* fin; int HWl, tilesHW, pbase;
        if (cb < CV0)               { fin = f0; HWl = HW0; tilesHW = CT0; pbase = PB0; }
        else if ((cb -= CV0) < CV1) { fin = f1; HWl = HW1; tilesHW = CT1; pbase = PB1; }
        else if ((cb -= CV1) < CV2) { fin = f2; HWl = HW2; tilesHW = CT2; pbase = PB2; }
        else       { cb -= CV2;       fin = f3; HWl = HW3; tilesHW = CT3; pbase = PB3; }
        const int nt  = tilesHW * 4;
        const int bc  = cb / nt;
        const int r   = cb % nt;
        const int hw0 = (r >> 2) * 64;
        const int c0  = (r & 3) * 64;
        unsigned (*t)[33] = (unsigned(*)[33])smraw;   // [64 px][33] uints = 8448B

        const float* ip = fin + (size_t)bc * 256 * HWl;
#pragma unroll
        for (int it = 0; it < 2; it++) {
            int idx = tid + it * 256;          // 0..511
            int rp = idx >> 4;                 // channel pair 0..31
            int q  = idx & 15;                 // px quad
            int hw = hw0 + q * 4;
            if (hw < HWl) {
                const float* p0 = ip + (size_t)(c0 + 2 * rp) * HWl + hw;
                float4 v0 = __ldcs((const float4*)p0);
                float4 v1 = __ldcs((const float4*)(p0 + HWl));
                __half2 h0 = __floats2half2_rn(v0.x, v1.x);
                __half2 h1 = __floats2half2_rn(v0.y, v1.y);
                __half2 h2 = __floats2half2_rn(v0.z, v1.z);
                __half2 h3 = __floats2half2_rn(v0.w, v1.w);
                t[q * 4 + 0][rp] = *(unsigned*)&h0;
                t[q * 4 + 1][rp] = *(unsigned*)&h1;
                t[q * 4 + 2][rp] = *(unsigned*)&h2;
                t[q * 4 + 3][rp] = *(unsigned*)&h3;
            }
        }
        __syncthreads();
        __half* op = g_nhwc + ((size_t)(pbase + bc * HWl)) * 256;
        {
            int px = tid >> 2;                 // 0..63
            int u  = tid & 3;                  // 0..3
            int hw = hw0 + px;
            if (hw < HWl) {
                unsigned w[8];
#pragma unroll
                for (int k = 0; k < 8; k++) w[k] = t[px][u * 8 + k];
                uint4 o0 = make_uint4(w[0], w[1], w[2], w[3]);
                uint4 o1 = make_uint4(w[4], w[5], w[6], w[7]);
                __half* dst = op + (size_t)hw * 256 + c0 + u * 16;
                *(uint4*)dst = o0;
                *(uint4*)(dst + 8) = o1;
            }
        }
    } else {
        // ------- w_out fp32 -> fp16 -------------------------------------
        int j = (blockIdx.x - GEMM_BLKS - CVTOT) * 256 + tid;
        float4 v = *(const float4*)(w_out + (size_t)j * 4);
        __half2 h0 = __floats2half2_rn(v.x, v.y);
        __half2 h1 = __floats2half2_rn(v.z, v.w);
        uint2 o;
        o.x = *(unsigned*)&h0;
        o.y = *(unsigned*)&h1;
        *(uint2*)(g_woutH + (size_t)j * 4) = o;
    }
}

// =====================================================================
// Fused aggregation: 128 threads / 4 warps; lane covers 8 channels
// (uint4 gathers); warps split the descriptor list 4 ways.
// =====================================================================
__global__ void __launch_bounds__(128) agg_kernel(
    const float* __restrict__ anchor, const float* __restrict__ proj,
    const float* __restrict__ wh, const float* __restrict__ b_fc)
{
    __shared__ float  s_w[NW];
    __shared__ float  s_uv[NCAM * NPT][2];
    __shared__ int4   s_dA[NDESC];
    __shared__ float4 s_dW[NDESC];
    __shared__ int    s_cnt[8];
    __shared__ float  s_acc[4][EDD];

    const int ba   = blockIdx.x;
    const int b    = ba / AA;
    const int tid  = threadIdx.x;
    const int wrp  = tid >> 5;
    const int lane = tid & 31;

    for (int i = tid; i < NW; i += 128) s_w[i] = g_w[(size_t)ba * NW + i] + b_fc[i];

    if (tid < NCAM * NPT) {
        const float fsx[7] = {0.f, 0.45f, -0.45f, 0.f, 0.f, 0.f, 0.f};
        const float fsy[7] = {0.f, 0.f, 0.f, 0.45f, -0.45f, 0.f, 0.f};
        const float fsz[7] = {0.f, 0.f, 0.f, 0.f, 0.f, 0.45f, -0.45f};
        int cam = tid / NPT, p = tid % NPT;
        const float* an = anchor + (size_t)ba * 8;
        float e0 = expf(an[3]), e1 = expf(an[4]), e2 = expf(an[5]);
        float k0 = fsx[p] * e0, k1 = fsy[p] * e1, k2 = fsz[p] * e2;
        float sn = an[6], cs = an[7];
        float X = cs * k0 - sn * k1 + an[0];
        float Y = sn * k0 + cs * k1 + an[1];
        float Z = k2 + an[2];
        const float* M = proj + (size_t)(b * NCAM + cam) * 16;
        float d0 = M[0] * X + M[1] * Y + M[2]  * Z + M[3];
        float d1 = M[4] * X + M[5] * Y + M[6]  * Z + M[7];
        float d2 = M[8] * X + M[9] * Y + M[10] * Z + M[11];
        float iz = 1.f / fmaxf(d2, 1e-5f);
        float x = d0 * iz / fmaxf(wh[(size_t)(b * NCAM + cam) * 2 + 0], 1e-5f);
        float y = d1 * iz / fmaxf(wh[(size_t)(b * NCAM + cam) * 2 + 1], 1e-5f);
        s_uv[tid][0] = x * 2.f - 1.f;
        s_uv[tid][1] = y * 2.f - 1.f;
    }
    __syncthreads();

#pragma unroll
    for (int q = 0; q < 2; q++) {
        int gg = wrp * 2 + q;
        float mx = -INFINITY;
        for (int cc = lane; cc < 168; cc += 32) mx = fmaxf(mx, s_w[cc * 8 + gg]);
#pragma unroll
        for (int o = 16; o; o >>= 1) mx = fmaxf(mx, __shfl_xor_sync(0xffffffffu, mx, o));
        float sum = 0.f;
        for (int cc = lane; cc < 168; cc += 32) {
            float e = expf(s_w[cc * 8 + gg] - mx);
            s_w[cc * 8 + gg] = e;
            sum += e;
        }
#pragma unroll
        for (int o = 16; o; o >>= 1) sum += __shfl_xor_sync(0xffffffffu, sum, o);
        float inv = 1.f / sum;
        for (int cc = lane; cc < 168; cc += 32) s_w[cc * 8 + gg] *= inv;
    }

    const int Hl[4]  = {64, 32, 16, 8};
    const int Wl[4]  = {176, 88, 44, 22};
    const int HWl[4] = {HW0, HW1, HW2, HW3};
    const int PBl[4] = {PB0, PB1, PB2, PB3};
    int4   dA2[2];
    float4 dW2[2];
    unsigned bal2[2];
    int flags = 0;
#pragma unroll
    for (int it = 0; it < 2; it++) {
        int d = it * 128 + tid;
        int flag = 0;
        if (d < NDESC) {
            int cam = d / (NPT * NLVL);
            int r   = d - cam * (NPT * NLVL);
            int p   = r >> 2;
            int lvl = r & 3;
            float u = s_uv[cam * NPT + p][0];
            float v = s_uv[cam * NPT + p][1];
            const int H = Hl[lvl], W = Wl[lvl];
            float gx = (u + 1.f) * (W * 0.5f) - 0.5f;
            float gy = (v + 1.f) * (H * 0.5f) - 0.5f;
            float x0f = floorf(gx), y0f = floorf(gy);
            float wx1 = gx - x0f, wy1 = gy - y0f;
            bool vx0 = (x0f >= 0.f)       && (x0f <= (float)(W - 1));
            bool vx1 = (x0f + 1.f >= 0.f) && (x0f + 1.f <= (float)(W - 1));
            bool vy0 = (y0f >= 0.f)       && (y0f <= (float)(H - 1));
            bool vy1 = (y0f + 1.f >= 0.f) && (y0f + 1.f <= (float)(H - 1));
            flag = ((vx0 || vx1) && (vy0 || vy1)) ? 1 : 0;
            int x0 = (int)fminf(fmaxf(x0f, 0.f),       (float)(W - 1));
            int x1 = (int)fminf(fmaxf(x0f + 1.f, 0.f), (float)(W - 1));
            int y0 = (int)fminf(fmaxf(y0f, 0.f),       (float)(H - 1));
            int y1 = (int)fminf(fmaxf(y0f + 1.f, 0.f), (float)(H - 1));
            dA2[it].x = PBl[lvl] + (b * NCAM + cam) * HWl[lvl] + y0 * W + x0;
            dA2[it].y = (x1 - x0) * 256;
            dA2[it].z = (y1 - y0) * W * 256;
            dA2[it].w = ((cam * NLVL + lvl) * NPT + p) * NGRP;
            dW2[it].x = (vx0 && vy0) ? (1.f - wx1) * (1.f - wy1) : 0.f;
            dW2[it].y = (vx1 && vy0) ? wx1 * (1.f - wy1)         : 0.f;
            dW2[it].z = (vx0 && vy1) ? (1.f - wx1) * wy1         : 0.f;
            dW2[it].w = (vx1 && vy1) ? wx1 * wy1                 : 0.f;
        }
        bal2[it] = __ballot_sync(0xffffffffu, flag);
        flags |= flag << it;
        if (lane == 0) s_cnt[it * 4 + wrp] = __popc(bal2[it]);
    }
    __syncthreads();

    int pfx[8];
    {
        int run = 0;
#pragma unroll
        for (int i = 0; i < 8; i++) { pfx[i] = run; run += s_cnt[i]; }
    }
    int cnt = pfx[7] + s_cnt[7];
#pragma unroll
    for (int it = 0; it < 2; it++) {
        if ((flags >> it) & 1) {
            int pos = pfx[it * 4 + wrp] + __popc(bal2[it] & ((1u << lane) - 1u));
            s_dA[pos] = dA2[it];
            s_dW[pos] = dW2[it];
        }
    }
    __syncthreads();

    const int g = lane >> 2;
    const __half* chan = g_nhwc + lane * 8;
    float a[8];
#pragma unroll
    for (int q = 0; q < 8; q++) a[q] = 0.f;

    for (int i = wrp; i < cnt; i += 4) {
        int4 D = s_dA[i];
        float4 wt = s_dW[i];
        const __half* bp = chan + (((size_t)D.x) << 8);
        uint4 r00 = *(const uint4*)(bp);
        uint4 r01 = *(const uint4*)(bp + D.y);
        uint4 r10 = *(const uint4*)(bp + D.z);
        uint4 r11 = *(const uint4*)(bp + D.z + D.y);
        float wf = s_w[D.w + g];
        const unsigned* p00 = &r00.x;
        const unsigned* p01 = &r01.x;
        const unsigned* p10 = &r10.x;
        const unsigned* p11 = &r11.x;
#pragma unroll
        for (int q = 0; q < 4; q++) {
            float2 v00 = __half22float2(*(const __half2*)&p00[q]);
            float2 v01 = __half22float2(*(const __half2*)&p01[q]);
            float2 v10 = __half22float2(*(const __half2*)&p10[q]);
            float2 v11 = __half22float2(*(const __half2*)&p11[q]);
            float sx = fmaf(wt.x, v00.x, fmaf(wt.y, v01.x, fmaf(wt.z, v10.x, wt.w * v11.x)));
            float sy = fmaf(wt.x, v00.y, fmaf(wt.y, v01.y, fmaf(wt.z, v10.y, wt.w * v11.y)));
            a[q * 2 + 0] = fmaf(sx, wf, a[q * 2 + 0]);
            a[q * 2 + 1] = fmaf(sy, wf, a[q * 2 + 1]);
        }
    }
#pragma unroll
    for (int q = 0; q < 8; q++) s_acc[wrp][lane * 8 + q] = a[q];
    __syncthreads();

    {
        int c = tid * 2;
        float o0 = s_acc[0][c + 0] + s_acc[1][c + 0] + s_acc[2][c + 0] + s_acc[3][c + 0];
        float o1 = s_acc[0][c + 1] + s_acc[1][c + 1] + s_acc[2][c + 1] + s_acc[3][c + 1];
        *(__half2*)(g_fusedH + (size_t)ba * EDD + c) = __floats2half2_rn(o0, o1);
    }
}

// =====================================================================
// Out-projection wmma: 32m x 64n tiles, 8 warps (2n x 4k split-K).
// =====================================================================
__global__ void __launch_bounds__(256) outproj_wmma(
    const float* __restrict__ bias, float* __restrict__ out)
{
    __shared__ __align__(16) float sm[4][32][72];
    const int bx = blockIdx.x;
    const int by = blockIdx.y;
    const int tid = threadIdx.x;
    const int wid = tid >> 5;
    const int wk  = wid >> 1;
    const int wn  = wid & 1;
    const int m0 = by * 32;
    const int n0 = bx * 64 + wn * 32;

    wmma::fragment<wmma::accumulator, 16, 16, 16, float> cf[2][2];
#pragma unroll
    for (int i = 0; i < 2; i++)
#pragma unroll
        for (int j = 0; j < 2; j++) wmma::fill_fragment(cf[i][j], 0.f);

    for (int k0 = wk * 64; k0 < wk * 64 + 64; k0 += 16) {
        wmma::fragment<wmma::matrix_a, 16, 16, 16, __half, wmma::row_major> af[2];
        wmma::fragment<wmma::matrix_b, 16, 16, 16, __half, wmma::col_major> bf[2];
#pragma unroll
        for (int i = 0; i < 2; i++)
            wmma::load_matrix_sync(af[i], g_fusedH + (size_t)(m0 + i * 16) * EDD + k0, EDD);
#pragma unroll
        for (int j = 0; j < 2; j++)
            wmma::load_matrix_sync(bf[j], g_woutH + (size_t)(n0 + j * 16) * EDD + k0, EDD);
#pragma unroll
        for (int i = 0; i < 2; i++)
#pragma unroll
            for (int j = 0; j < 2; j++)
                wmma::mma_sync(cf[i][j], af[i], bf[j], cf[i][j]);
    }
#pragma unroll
    for (int i = 0; i < 2; i++)
#pragma unroll
        for (int j = 0; j < 2; j++)
            wmma::store_matrix_sync(&sm[wk][i * 16][wn * 32 + j * 16],
                                    cf[i][j], 72, wmma::mem_row_major);
    __syncthreads();

    const int c = (tid & 15) * 4;
    float4 bb = *(const float4*)(bias + bx * 64 + c);
    for (int r = (tid >> 4); r < 32; r += 16) {
        int m = by * 32 + r;
        if (m >= NBA) break;
        float4 o;
        o.x = sm[0][r][c + 0] + sm[1][r][c + 0] + sm[2][r][c + 0] + sm[3][r][c + 0] + bb.x;
        o.y = sm[0][r][c + 1] + sm[1][r][c + 1] + sm[2][r][c + 1] + sm[3][r][c + 1] + bb.y;
        o.z = sm[0][r][c + 2] + sm[1][r][c + 2] + sm[2][r][c + 2] + sm[3][r][c + 2] + bb.z;
        o.w = sm[0][r][c + 3] + sm[1][r][c + 3] + sm[2][r][c + 3] + sm[3][r][c + 3] + bb.w;
        *(float4*)(out + (size_t)m * EDD + bx * 64 + c) = o;
    }
}

// =====================================================================
// launch
// =====================================================================
extern "C" void kernel_launch(void* const* d_in, const int* in_sizes, int n_in,
                              void* d_out, int out_size)
{
    const float* inst   = (const float*)d_in[0];
    const float* anchor = (const float*)d_in[1];
    const float* emb    = (const float*)d_in[2];
    const float* f0     = (const float*)d_in[3];
    const float* f1     = (const float*)d_in[4];
    const float* f2     = (const float*)d_in[5];
    const float* f3     = (const float*)d_in[6];
    const float* proj   = (const float*)d_in[7];
    const float* wh     = (const float*)d_in[8];
    const float* w_fc   = (const float*)d_in[9];
    const float* b_fc   = (const float*)d_in[10];
    const float* w_out  = (const float*)d_in[11];
    const float* b_out  = (const float*)d_in[12];
    float* out = (float*)d_out;

    fused_kernel<<<GEMM_BLKS + CVTOT + WOUT_BLKS, 256>>>(
        inst, emb, w_fc, w_out, f0, f1, f2, f3);
    agg_kernel<<<NBA, 128>>>(anchor, proj, wh, b_fc);
    outproj_wmma<<<dim3(EDD / 64, MPAD / 32), 256>>>(b_out, out);
}